// round 1
// baseline (speedup 1.0000x reference)
#include <cuda_runtime.h>
#include <cstdint>

// GENConv fused kernel: gather + relu + softmax_sg aggregation + linear.
//
// msg  = relu(x[src]) + 1e-7            [E, 64]
// a    = softmax over edges per dst of (beta * msg)    (shift-invariant, logits
//        bounded in [1e-7*beta, ~6*beta] so NO max-subtraction needed)
// h[n] = sum_e msg * a                  [N, 64]
// out  = h @ W^T + b                    [N, 64]
//
// Pass A (edge_kernel): per (edge, quad-of-4-features) thread,
//   s[n,d] += exp(beta*msg),  t[n,d] += msg*exp(beta*msg)
//   accumulated via red.global.add.v4.f32 (one vector reduction per array).
// Pass B (gemm_kernel): h = t/s (0 for empty segments), out = h @ W^T + b.

#define EPS 1e-7f

constexpr int MAX_N = 50000;
constexpr int D     = 64;

__device__ float g_s[(size_t)MAX_N * D];
__device__ float g_t[(size_t)MAX_N * D];

__device__ __forceinline__ void red_add_v4(float* p, float a, float b, float c, float d) {
    asm volatile("red.global.add.v4.f32 [%0], {%1, %2, %3, %4};"
                 :: "l"(p), "f"(a), "f"(b), "f"(c), "f"(d)
                 : "memory");
}

__global__ void __launch_bounds__(256)
edge_kernel(const float* __restrict__ x,
            const int*   __restrict__ ei,     // [2, E]: row0 = dst, row1 = src
            const float* __restrict__ beta_p,
            int E)
{
    int tid = blockIdx.x * blockDim.x + threadIdx.x;
    int e = tid >> 4;          // edge id
    if (e >= E) return;
    int q = tid & 15;          // which float4 of the 64-wide row

    float beta = __ldg(beta_p);
    int dst = __ldg(ei + e);
    int src = __ldg(ei + E + e);

    float4 xv = __ldg(reinterpret_cast<const float4*>(x + (size_t)src * D) + q);

    float m0 = fmaxf(xv.x, 0.f) + EPS;
    float m1 = fmaxf(xv.y, 0.f) + EPS;
    float m2 = fmaxf(xv.z, 0.f) + EPS;
    float m3 = fmaxf(xv.w, 0.f) + EPS;

    // bounded logits -> direct exp is numerically safe
    float e0 = __expf(beta * m0);
    float e1 = __expf(beta * m1);
    float e2 = __expf(beta * m2);
    float e3 = __expf(beta * m3);

    size_t off = (size_t)dst * D + (q << 2);
    red_add_v4(g_s + off, e0, e1, e2, e3);
    red_add_v4(g_t + off, m0 * e0, m1 * e1, m2 * e2, m3 * e3);
}

// out[n][j] = b[j] + sum_d (t[n][d]/s[n][d]) * W[j][d]
// Block = 256 threads = 4 nodes x 64 output features per tile.
// Each thread keeps W[j][0..63] in registers; h tile staged in smem,
// read back as warp-uniform float4 (LDS broadcast, conflict-free).
__global__ void __launch_bounds__(256)
gemm_kernel(const float* __restrict__ W,
            const float* __restrict__ bvec,
            float*       __restrict__ out,
            int N)
{
    __shared__ float hs[4][D];

    int j  = threadIdx.x & 63;   // output feature (also d in the load phase)
    int nl = threadIdx.x >> 6;   // node-in-tile (0..3)

    float4 w[16];
    const float4* Wr = reinterpret_cast<const float4*>(W + (size_t)j * D);
    #pragma unroll
    for (int k = 0; k < 16; k++) w[k] = __ldg(Wr + k);
    float bj = __ldg(bvec + j);

    int ntiles = (N + 3) >> 2;
    for (int tile = blockIdx.x; tile < ntiles; tile += gridDim.x) {
        int n = (tile << 2) + nl;

        // finalize h = t/s for this tile (one division per (n,d), done once)
        float h = 0.f;
        if (n < N) {
            size_t off = (size_t)n * D + j;   // j doubles as feature index here
            float sv = g_s[off];
            float tv = g_t[off];
            h = (sv > 0.f) ? (tv / sv) : 0.f;
        }
        __syncthreads();          // protect hs against previous tile's readers
        hs[nl][j] = h;
        __syncthreads();

        if (n < N) {
            float acc = bj;
            const float4* hv = reinterpret_cast<const float4*>(hs[nl]);
            #pragma unroll
            for (int k = 0; k < 16; k++) {
                float4 hh = hv[k];     // warp-uniform address -> broadcast
                acc += hh.x * w[k].x + hh.y * w[k].y
                     + hh.z * w[k].z + hh.w * w[k].w;
            }
            out[(size_t)n * D + j] = acc;
        }
    }
}

extern "C" void kernel_launch(void* const* d_in, const int* in_sizes, int n_in,
                              void* d_out, int out_size)
{
    const float* x    = (const float*)d_in[0];   // [N, 64]
    const float* W    = (const float*)d_in[1];   // [64, 64]
    const float* bvec = (const float*)d_in[2];   // [64]
    const float* beta = (const float*)d_in[3];   // [1]
    const int*   ei   = (const int*)  d_in[4];   // [2, E]

    int N = in_sizes[0] / D;
    int E = in_sizes[4] / 2;
    float* out = (float*)d_out;

    void *sp = nullptr, *tp = nullptr;
    cudaGetSymbolAddress(&sp, g_s);
    cudaGetSymbolAddress(&tp, g_t);
    size_t bytes = (size_t)N * D * sizeof(float);
    cudaMemsetAsync(sp, 0, bytes);
    cudaMemsetAsync(tp, 0, bytes);

    long long threads = (long long)E * 16;
    int blocks = (int)((threads + 255) / 256);
    edge_kernel<<<blocks, 256>>>(x, ei, beta, E);

    gemm_kernel<<<1184, 256>>>(W, bvec, out, N);
}

// round 2
// speedup vs baseline: 1.2488x; 1.2488x over previous
#include <cuda_runtime.h>
#include <cstdint>

// GENConv fused: gather + relu + softmax_sg aggregation + linear.
//
// Pass A (edge_kernel): s[n,d] += exp(beta*m), t[n,d] += m*exp(beta*m)
//   via red.global.add.v4.f32 (logits bounded -> no max-subtraction needed).
// Pass B (gemm_kernel): h = t/s (0 if empty), out = h @ W^T + b.
//   16-node tiles, prefetched; W rows in registers; 4 interleaved acc chains.

#define EPS 1e-7f

constexpr int MAX_N = 50000;
constexpr int D     = 64;

__device__ float g_s[(size_t)MAX_N * D];
__device__ float g_t[(size_t)MAX_N * D];

__device__ __forceinline__ void red_add_v4(float* p, float a, float b, float c, float d) {
    asm volatile("red.global.add.v4.f32 [%0], {%1, %2, %3, %4};"
                 :: "l"(p), "f"(a), "f"(b), "f"(c), "f"(d)
                 : "memory");
}

__global__ void __launch_bounds__(256)
edge_kernel(const float* __restrict__ x,
            const int*   __restrict__ ei,     // [2, E]: row0 = dst, row1 = src
            const float* __restrict__ beta_p,
            int E)
{
    int tid = blockIdx.x * blockDim.x + threadIdx.x;
    int e = tid >> 4;          // edge id
    if (e >= E) return;
    int q = tid & 15;          // which float4 of the 64-wide row

    float beta = __ldg(beta_p);
    int dst = __ldg(ei + e);
    int src = __ldg(ei + E + e);

    float4 xv = __ldg(reinterpret_cast<const float4*>(x + (size_t)src * D) + q);

    float m0 = fmaxf(xv.x, 0.f) + EPS;
    float m1 = fmaxf(xv.y, 0.f) + EPS;
    float m2 = fmaxf(xv.z, 0.f) + EPS;
    float m3 = fmaxf(xv.w, 0.f) + EPS;

    float e0 = __expf(beta * m0);
    float e1 = __expf(beta * m1);
    float e2 = __expf(beta * m2);
    float e3 = __expf(beta * m3);

    size_t off = (size_t)dst * D + (q << 2);
    red_add_v4(g_s + off, e0, e1, e2, e3);
    red_add_v4(g_t + off, m0 * e0, m1 * e1, m2 * e2, m3 * e3);
}

// out[n][j] = b[j] + sum_d (t[n][d]/s[n][d]) * W[j][d]
// Block 256 = (j = tid&63 output feature) x (nl = tid>>6 node lane 0..3).
// Tile = 16 nodes: each thread loads 4 (s,t) pairs (coalesced), finalizes h,
// stages in smem; next tile's loads are prefetched past the barrier so the
// global latency overlaps the 256-FFMA compute phase (4 independent chains).
__global__ void __launch_bounds__(256)
gemm_kernel(const float* __restrict__ sA,
            const float* __restrict__ tA,
            const float* __restrict__ W,
            const float* __restrict__ bvec,
            float*       __restrict__ out,
            int N)
{
    __shared__ float hs[16][D];

    int j  = threadIdx.x & 63;   // output feature (also d index in load phase)
    int nl = threadIdx.x >> 6;   // node lane (0..3)

    float4 w[16];
    const float4* Wr = reinterpret_cast<const float4*>(W + (size_t)j * D);
    #pragma unroll
    for (int k = 0; k < 16; k++) w[k] = __ldg(Wr + k);
    float bj = __ldg(bvec + j);

    int ntiles = (N + 15) >> 4;

    float sv[4], tv[4];
    int tile = blockIdx.x;

    if (tile < ntiles) {
        #pragma unroll
        for (int i = 0; i < 4; i++) {
            int n = (tile << 4) + nl + (i << 2);
            bool ok = n < N;
            size_t off = (size_t)n * D + j;
            sv[i] = ok ? __ldg(sA + off) : 1.f;
            tv[i] = ok ? __ldg(tA + off) : 0.f;
        }
    }

    while (tile < ntiles) {
        float h[4];
        #pragma unroll
        for (int i = 0; i < 4; i++)
            h[i] = (sv[i] > 0.f) ? __fdividef(tv[i], sv[i]) : 0.f;

        __syncthreads();           // previous tile's readers done
        #pragma unroll
        for (int i = 0; i < 4; i++)
            hs[nl + (i << 2)][j] = h[i];
        __syncthreads();           // tile staged

        int next = tile + gridDim.x;
        if (next < ntiles) {       // prefetch next tile (overlaps compute below)
            #pragma unroll
            for (int i = 0; i < 4; i++) {
                int n = (next << 4) + nl + (i << 2);
                bool ok = n < N;
                size_t off = (size_t)n * D + j;
                sv[i] = ok ? __ldg(sA + off) : 1.f;
                tv[i] = ok ? __ldg(tA + off) : 0.f;
            }
        }

        // 4 interleaved dot-product chains (nodes nl, nl+4, nl+8, nl+12)
        float acc0 = bj, acc1 = bj, acc2 = bj, acc3 = bj;
        const float4* hv0 = reinterpret_cast<const float4*>(hs[nl]);
        const float4* hv1 = reinterpret_cast<const float4*>(hs[nl + 4]);
        const float4* hv2 = reinterpret_cast<const float4*>(hs[nl + 8]);
        const float4* hv3 = reinterpret_cast<const float4*>(hs[nl + 12]);
        #pragma unroll
        for (int k = 0; k < 16; k++) {
            float4 a = hv0[k], b = hv1[k], c = hv2[k], d = hv3[k];
            acc0 = fmaf(a.x, w[k].x, acc0); acc1 = fmaf(b.x, w[k].x, acc1);
            acc2 = fmaf(c.x, w[k].x, acc2); acc3 = fmaf(d.x, w[k].x, acc3);
            acc0 = fmaf(a.y, w[k].y, acc0); acc1 = fmaf(b.y, w[k].y, acc1);
            acc2 = fmaf(c.y, w[k].y, acc2); acc3 = fmaf(d.y, w[k].y, acc3);
            acc0 = fmaf(a.z, w[k].z, acc0); acc1 = fmaf(b.z, w[k].z, acc1);
            acc2 = fmaf(c.z, w[k].z, acc2); acc3 = fmaf(d.z, w[k].z, acc3);
            acc0 = fmaf(a.w, w[k].w, acc0); acc1 = fmaf(b.w, w[k].w, acc1);
            acc2 = fmaf(c.w, w[k].w, acc2); acc3 = fmaf(d.w, w[k].w, acc3);
        }

        int nbase = tile << 4;
        if (nbase + nl      < N) out[(size_t)(nbase + nl     ) * D + j] = acc0;
        if (nbase + nl + 4  < N) out[(size_t)(nbase + nl + 4 ) * D + j] = acc1;
        if (nbase + nl + 8  < N) out[(size_t)(nbase + nl + 8 ) * D + j] = acc2;
        if (nbase + nl + 12 < N) out[(size_t)(nbase + nl + 12) * D + j] = acc3;

        tile = next;
    }
}

extern "C" void kernel_launch(void* const* d_in, const int* in_sizes, int n_in,
                              void* d_out, int out_size)
{
    const float* x    = (const float*)d_in[0];   // [N, 64]
    const float* W    = (const float*)d_in[1];   // [64, 64]
    const float* bvec = (const float*)d_in[2];   // [64]
    const float* beta = (const float*)d_in[3];   // [1]
    const int*   ei   = (const int*)  d_in[4];   // [2, E]

    int N = in_sizes[0] / D;
    int E = in_sizes[4] / 2;
    float* out = (float*)d_out;

    void *sp = nullptr, *tp = nullptr;
    cudaGetSymbolAddress(&sp, g_s);
    cudaGetSymbolAddress(&tp, g_t);
    size_t bytes = (size_t)N * D * sizeof(float);
    cudaMemsetAsync(sp, 0, bytes);
    cudaMemsetAsync(tp, 0, bytes);

    long long threads = (long long)E * 16;
    int blocks = (int)((threads + 255) / 256);
    edge_kernel<<<blocks, 256>>>(x, ei, beta, E);

    gemm_kernel<<<592, 256>>>((const float*)sp, (const float*)tp, W, bvec, out, N);
}